// round 5
// baseline (speedup 1.0000x reference)
#include <cuda_runtime.h>
#include <cuda_bf16.h>
#include <math.h>

// Problem constants
#define BB   32      // batch
#define SS   64      // src len
#define TT   64      // tgt len (63 decode steps)
#define EE   512     // embed dim
#define HH   512     // encoder hidden per dir
#define DDm  1024    // 2*H
#define VV   32000   // vocab

// ---------------------------------------------------------------------------
// Static device scratch (allocation-free rule)
// ---------------------------------------------------------------------------
__device__ __align__(16) float g_embx [BB*SS*EE];          // 4 MB
__device__ __align__(16) float g_xgF  [BB*SS*4*HH];        // 16 MB
__device__ __align__(16) float g_xgB  [BB*SS*4*HH];        // 16 MB
__device__ __align__(16) float g_in1  [BB*SS*DDm];         // 8 MB
__device__ __align__(16) float g_enc  [BB*SS*DDm];         // 8 MB
__device__ __align__(16) float g_Uenc [BB*SS*DDm];         // 8 MB
__device__ __align__(16) float g_hbuf [2*2*2*BB*HH];       // [layer][dir][pp][b*512+j]
__device__ __align__(16) float g_c    [2*2*BB*HH];         // [layer][dir][b*512+j]
__device__ __align__(16) float g_dh0  [BB*DDm];
__device__ __align__(16) float g_dc0  [BB*DDm];
__device__ __align__(16) float g_dh1  [BB*DDm];
__device__ __align__(16) float g_dc1  [BB*DDm];
__device__ __align__(16) float g_q    [BB*DDm];
__device__ __align__(16) float g_sc   [BB*SS];
__device__ __align__(16) float g_xcat [BB*(EE+DDm)];       // [32][1536]
__device__ __align__(16) float g_gates[BB*4*DDm];          // [32][4096]
__device__ __align__(16) float g_H1   [63*BB*DDm];         // 8.25 MB

__device__ __forceinline__ float sigf(float v) { return 1.0f/(1.0f + expf(-v)); }

// ---------------------------------------------------------------------------
// 1) embedding gather with source reversal: embx[b][s][:] = emb_src[x[b][S-1-s]]
// ---------------------------------------------------------------------------
__global__ void embed_rev_kernel(const int* __restrict__ x,
                                 const float* __restrict__ emb_src) {
    int bs = blockIdx.x;                 // b*64 + s
    int b = bs >> 6, s = bs & 63;
    int tok = x[b*SS + (SS-1 - s)];
    const float4* src = (const float4*)(emb_src + (size_t)tok*EE);
    float4* dst = (float4*)(g_embx + (size_t)bs*EE);
    for (int i = threadIdx.x; i < EE/4; i += blockDim.x) dst[i] = src[i];
}

// ---------------------------------------------------------------------------
// 2) SGEMM (TN): C[m][n] = sum_k A[m][k]*W[n][k] + bias[n]
//    BM=BN=128, BK=8, 256 threads, 8x8 per thread.
//    grid.x = M tiles (so a wave shares W tiles -> W streamed ~once from DRAM)
//    remap=1: output row r=(t*32+b) is written to row (b*63+t)   (logits layout)
//    N must be a multiple of 128 (true for all uses). M guarded.
// ---------------------------------------------------------------------------
__global__ __launch_bounds__(256) void sgemm128(
    const float* __restrict__ A, const float* __restrict__ W,
    const float* __restrict__ bias, float* __restrict__ C,
    int M, int N, int K, int remap)
{
    __shared__ float As[8][132];
    __shared__ float Ws[8][132];
    int tid = threadIdx.x;
    int tx = tid & 15;          // N: 8 cols at n0 + tx*8
    int ty = tid >> 4;          // M: 8 rows at m0 + ty*8
    int m0 = blockIdx.x * 128;
    int n0 = blockIdx.y * 128;

    float acc[8][8];
    #pragma unroll
    for (int i = 0; i < 8; i++)
        #pragma unroll
        for (int j = 0; j < 8; j++) acc[i][j] = 0.f;

    int lr  = tid >> 1;         // 0..127
    int lk  = (tid & 1) * 4;    // 0 or 4

    for (int k0 = 0; k0 < K; k0 += 8) {
        // load A tile 128x8 (guard M)
        float4 va;
        int gm = m0 + lr;
        if (gm < M) va = *(const float4*)(A + (size_t)gm*K + k0 + lk);
        else        va = make_float4(0.f,0.f,0.f,0.f);
        As[lk+0][lr]=va.x; As[lk+1][lr]=va.y; As[lk+2][lr]=va.z; As[lk+3][lr]=va.w;
        // load W tile 128x8 (N multiple of 128, no guard)
        float4 vw = *(const float4*)(W + (size_t)(n0+lr)*K + k0 + lk);
        Ws[lk+0][lr]=vw.x; Ws[lk+1][lr]=vw.y; Ws[lk+2][lr]=vw.z; Ws[lk+3][lr]=vw.w;
        __syncthreads();

        #pragma unroll
        for (int kk = 0; kk < 8; kk++) {
            float a[8], w[8];
            #pragma unroll
            for (int i = 0; i < 8; i++) a[i] = As[kk][ty*8+i];
            #pragma unroll
            for (int j = 0; j < 8; j++) w[j] = Ws[kk][tx*8+j];
            #pragma unroll
            for (int i = 0; i < 8; i++)
                #pragma unroll
                for (int j = 0; j < 8; j++)
                    acc[i][j] += a[i]*w[j];
        }
        __syncthreads();
    }

    #pragma unroll
    for (int i = 0; i < 8; i++) {
        int gm = m0 + ty*8 + i;
        if (gm >= M) continue;
        int orow = gm;
        if (remap) orow = (gm & 31)*63 + (gm >> 5);   // r=t*32+b -> b*63+t
        float* cr = C + (size_t)orow*N + n0 + tx*8;
        #pragma unroll
        for (int j = 0; j < 8; j++)
            cr[j] = acc[i][j] + bias[n0 + tx*8 + j];
    }
}

// ---------------------------------------------------------------------------
// 3) Skinny SGEMM for M=32 (decoder): C[32][N] (+)= A[32][K] * W[N][K]^T (+bias)
//    BN=64, BK=16, 256 threads, 2x4 per thread. accflag=1: C += (no bias).
// ---------------------------------------------------------------------------
__global__ __launch_bounds__(256) void sgemm32(
    const float* __restrict__ A, const float* __restrict__ W,
    const float* __restrict__ bias, float* __restrict__ C,
    int N, int K, int accflag)
{
    __shared__ float As[16][33];
    __shared__ float Ws[16][68];
    int tid = threadIdx.x;
    int tx = tid & 15;          // N: 4 cols at n0 + tx*4
    int ty = tid >> 4;          // M: 2 rows at ty*2
    int n0 = blockIdx.x * 64;

    float acc[2][4] = {{0.f,0.f,0.f,0.f},{0.f,0.f,0.f,0.f}};

    int ar = tid >> 3;          // 0..31
    int ak = (tid & 7) * 2;     // 0..14
    int wr = tid >> 2;          // 0..63
    int wk = (tid & 3) * 4;     // 0..12

    for (int k0 = 0; k0 < K; k0 += 16) {
        float2 va = *(const float2*)(A + (size_t)ar*K + k0 + ak);
        As[ak][ar] = va.x; As[ak+1][ar] = va.y;
        float4 vw = *(const float4*)(W + (size_t)(n0+wr)*K + k0 + wk);
        Ws[wk+0][wr]=vw.x; Ws[wk+1][wr]=vw.y; Ws[wk+2][wr]=vw.z; Ws[wk+3][wr]=vw.w;
        __syncthreads();
        #pragma unroll
        for (int kk = 0; kk < 16; kk++) {
            float a0 = As[kk][ty*2], a1 = As[kk][ty*2+1];
            float w0 = Ws[kk][tx*4+0], w1 = Ws[kk][tx*4+1];
            float w2 = Ws[kk][tx*4+2], w3 = Ws[kk][tx*4+3];
            acc[0][0]+=a0*w0; acc[0][1]+=a0*w1; acc[0][2]+=a0*w2; acc[0][3]+=a0*w3;
            acc[1][0]+=a1*w0; acc[1][1]+=a1*w1; acc[1][2]+=a1*w2; acc[1][3]+=a1*w3;
        }
        __syncthreads();
    }

    #pragma unroll
    for (int i = 0; i < 2; i++) {
        int m = ty*2 + i;
        float* cr = C + (size_t)m*N + n0 + tx*4;
        #pragma unroll
        for (int j = 0; j < 4; j++) {
            float v = acc[i][j];
            if (accflag) v += cr[j];
            else         v += bias[n0 + tx*4 + j];
            cr[j] = v;
        }
    }
}

// ---------------------------------------------------------------------------
// 4) Encoder recurrence step. One launch per time step, both directions
//    (blockIdx.y = dir). Block: 256 thr = 32 batch x 8 j. blockIdx.x 0..63.
//    h ping-pong: reads pp=step&1, writes pp^1 (avoids cross-block races).
// ---------------------------------------------------------------------------
__global__ __launch_bounds__(256) void enc_step(
    const float* __restrict__ whhF, const float* __restrict__ whhB,
    int layer, int step)
{
    __shared__ float sh[256*33];   // h chunk transposed [k][b]
    int tid = threadIdx.x;
    int dir = blockIdx.y;
    const float* whh = dir ? whhB : whhF;
    const float* xg  = dir ? g_xgB : g_xgF;
    int pp = step & 1;
    const float* hin  = g_hbuf + (size_t)(((layer*2+dir)*2) + pp)    * (BB*HH);
    float*       hout = g_hbuf + (size_t)(((layer*2+dir)*2) + (pp^1))* (BB*HH);
    float*       cb   = g_c    + (size_t)(layer*2+dir) * (BB*HH);
    float*       outb = layer ? g_enc : g_in1;
    int s = dir ? (63 - step) : step;

    int b = tid & 31;
    int j = blockIdx.x*8 + (tid >> 5);

    float a0=0.f, a1=0.f, a2=0.f, a3=0.f;
    for (int ch = 0; ch < 2; ch++) {
        for (int i = tid; i < 256*32; i += 256) {
            int bb = i >> 8, kk = i & 255;
            sh[kk*33 + bb] = hin[bb*HH + ch*256 + kk];
        }
        __syncthreads();
        const float4* w0 = (const float4*)(whh + (size_t)(0*HH + j)*HH + ch*256);
        const float4* w1 = (const float4*)(whh + (size_t)(1*HH + j)*HH + ch*256);
        const float4* w2 = (const float4*)(whh + (size_t)(2*HH + j)*HH + ch*256);
        const float4* w3 = (const float4*)(whh + (size_t)(3*HH + j)*HH + ch*256);
        #pragma unroll 4
        for (int k4 = 0; k4 < 64; k4++) {
            float4 v0 = w0[k4], v1 = w1[k4], v2 = w2[k4], v3 = w3[k4];
            float h0 = sh[(k4*4+0)*33 + b];
            float h1 = sh[(k4*4+1)*33 + b];
            float h2 = sh[(k4*4+2)*33 + b];
            float h3 = sh[(k4*4+3)*33 + b];
            a0 += v0.x*h0 + v0.y*h1 + v0.z*h2 + v0.w*h3;
            a1 += v1.x*h0 + v1.y*h1 + v1.z*h2 + v1.w*h3;
            a2 += v2.x*h0 + v2.y*h1 + v2.z*h2 + v2.w*h3;
            a3 += v3.x*h0 + v3.y*h1 + v3.z*h2 + v3.w*h3;
        }
        __syncthreads();
    }

    size_t row = (size_t)(b*SS + s) * (4*HH);
    float gi = xg[row + 0*HH + j] + a0;
    float gf = xg[row + 1*HH + j] + a1;
    float gg = xg[row + 2*HH + j] + a2;
    float go = xg[row + 3*HH + j] + a3;
    float cc = sigf(gf)*cb[b*HH + j] + sigf(gi)*tanhf(gg);
    float hh = sigf(go)*tanhf(cc);
    cb[b*HH + j] = cc;
    hout[b*HH + j] = hh;
    outb[(size_t)(b*SS + s)*DDm + dir*HH + j] = hh;
}

// ---------------------------------------------------------------------------
// 5) Decoder initial state: concat encoder finals (pp=0 holds step-64 state)
// ---------------------------------------------------------------------------
__global__ void dec_init() {
    int idx = blockIdx.x*256 + threadIdx.x;       // 0..16383 = b*512+j
    if (idx >= BB*HH) return;
    int b = idx >> 9, j = idx & 511;
    const int NP = BB*HH;
    float h0f = g_hbuf[(size_t)((0*2+0)*2+0)*NP + idx];
    float h0b = g_hbuf[(size_t)((0*2+1)*2+0)*NP + idx];
    float h1f = g_hbuf[(size_t)((1*2+0)*2+0)*NP + idx];
    float h1b = g_hbuf[(size_t)((1*2+1)*2+0)*NP + idx];
    float c0f = g_c[(size_t)(0*2+0)*NP + idx];
    float c0b = g_c[(size_t)(0*2+1)*NP + idx];
    float c1f = g_c[(size_t)(1*2+0)*NP + idx];
    float c1b = g_c[(size_t)(1*2+1)*NP + idx];
    g_dh0[b*DDm + j]       = h0f;  g_dh0[b*DDm + HH + j] = h0b;
    g_dc0[b*DDm + j]       = c0f;  g_dc0[b*DDm + HH + j] = c0b;
    g_dh1[b*DDm + j]       = h1f;  g_dh1[b*DDm + HH + j] = h1b;
    g_dc1[b*DDm + j]       = c1f;  g_dc1[b*DDm + HH + j] = c1b;
}

// ---------------------------------------------------------------------------
// 6) attention scores: sc[b][s] = sum_e va[e]*tanh(q[b][e] + Uenc[b][s][e])
// ---------------------------------------------------------------------------
__global__ __launch_bounds__(256) void att_scores(const float* __restrict__ va) {
    __shared__ float red[256];
    int bs = blockIdx.x;
    int b = bs >> 6;
    const float* u  = g_Uenc + (size_t)bs*DDm;
    const float* qq = g_q + (size_t)b*DDm;
    int tid = threadIdx.x;
    float p = 0.f;
    for (int e = tid; e < DDm; e += 256)
        p += va[e]*tanhf(qq[e] + u[e]);
    red[tid] = p; __syncthreads();
    for (int off = 128; off > 0; off >>= 1) {
        if (tid < off) red[tid] += red[tid+off];
        __syncthreads();
    }
    if (tid == 0) g_sc[bs] = red[0];
}

// ---------------------------------------------------------------------------
// 7) softmax over s + context + target-embedding gather -> g_xcat[32][1536]
// ---------------------------------------------------------------------------
__global__ __launch_bounds__(256) void softmax_ctx(
    const int* __restrict__ y, const float* __restrict__ emb_tgt, int t)
{
    __shared__ float w[SS];
    int b = blockIdx.x;
    int tid = threadIdx.x;
    if (tid < SS) w[tid] = g_sc[b*SS + tid];
    __syncthreads();
    if (tid == 0) {
        float mx = w[0];
        for (int s = 1; s < SS; s++) mx = fmaxf(mx, w[s]);
        float sm = 0.f;
        for (int s = 0; s < SS; s++) { w[s] = expf(w[s]-mx); sm += w[s]; }
        float inv = 1.0f/sm;
        for (int s = 0; s < SS; s++) w[s] *= inv;
    }
    __syncthreads();
    // context
    for (int d = tid; d < DDm; d += 256) {
        float acc = 0.f;
        const float* e = g_enc + (size_t)(b*SS)*DDm + d;
        #pragma unroll 4
        for (int s = 0; s < SS; s++) acc += w[s]*e[(size_t)s*DDm];
        g_xcat[(size_t)b*(EE+DDm) + EE + d] = acc;
    }
    // embedding gather
    int tok = y[b*TT + t];
    const float* es = emb_tgt + (size_t)tok*EE;
    for (int e = tid; e < EE; e += 256)
        g_xcat[(size_t)b*(EE+DDm) + e] = es[e];
}

// ---------------------------------------------------------------------------
// 8) LSTM cell pointwise update (decoder): gates[32][4096] -> (c,h); opt. H1
// ---------------------------------------------------------------------------
__global__ void cell_update(float* __restrict__ cbuf, float* __restrict__ hbuf,
                            float* __restrict__ H1, int t)
{
    int idx = blockIdx.x*256 + threadIdx.x;   // 0..32767
    if (idx >= BB*DDm) return;
    int b = idx >> 10, j = idx & 1023;
    const float* g = g_gates + (size_t)b*4*DDm;
    float gi = g[j], gf = g[DDm + j], gg = g[2*DDm + j], go = g[3*DDm + j];
    float cc = sigf(gf)*cbuf[idx] + sigf(gi)*tanhf(gg);
    float hh = sigf(go)*tanhf(cc);
    cbuf[idx] = cc;
    hbuf[idx] = hh;
    if (H1) H1[((size_t)t*BB + b)*DDm + j] = hh;
}

// ---------------------------------------------------------------------------
// host driver
// ---------------------------------------------------------------------------
static float* symf(const void* s) {
    void* p = nullptr;
    cudaGetSymbolAddress(&p, s);
    return (float*)p;
}

extern "C" void kernel_launch(void* const* d_in, const int* in_sizes, int n_in,
                              void* d_out, int out_size) {
    const int*   x        = (const int*)  d_in[0];
    const int*   y        = (const int*)  d_in[1];
    const float* emb_src  = (const float*)d_in[2];
    const float* emb_tgt  = (const float*)d_in[3];
    const float* e0f_wih  = (const float*)d_in[4];
    const float* e0f_whh  = (const float*)d_in[5];
    const float* e0f_b    = (const float*)d_in[6];
    const float* e0b_wih  = (const float*)d_in[7];
    const float* e0b_whh  = (const float*)d_in[8];
    const float* e0b_b    = (const float*)d_in[9];
    const float* e1f_wih  = (const float*)d_in[10];
    const float* e1f_whh  = (const float*)d_in[11];
    const float* e1f_b    = (const float*)d_in[12];
    const float* e1b_wih  = (const float*)d_in[13];
    const float* e1b_whh  = (const float*)d_in[14];
    const float* e1b_b    = (const float*)d_in[15];
    const float* Wa_w     = (const float*)d_in[16];
    const float* Wa_b     = (const float*)d_in[17];
    const float* Ua_w     = (const float*)d_in[18];
    const float* Ua_b     = (const float*)d_in[19];
    const float* va_w     = (const float*)d_in[20];
    const float* d0_wih   = (const float*)d_in[21];
    const float* d0_whh   = (const float*)d_in[22];
    const float* d0_b     = (const float*)d_in[23];
    const float* d1_wih   = (const float*)d_in[24];
    const float* d1_whh   = (const float*)d_in[25];
    const float* d1_b     = (const float*)d_in[26];
    const float* fc_w     = (const float*)d_in[27];
    const float* fc_b     = (const float*)d_in[28];
    float* out = (float*)d_out;

    float* p_embx = symf(g_embx);
    float* p_xgF  = symf(g_xgF);
    float* p_xgB  = symf(g_xgB);
    float* p_in1  = symf(g_in1);
    float* p_enc  = symf(g_enc);
    float* p_Uenc = symf(g_Uenc);
    float* p_hbuf = symf(g_hbuf);
    float* p_c    = symf(g_c);
    float* p_dh0  = symf(g_dh0);
    float* p_dc0  = symf(g_dc0);
    float* p_dh1  = symf(g_dh1);
    float* p_dc1  = symf(g_dc1);
    float* p_q    = symf(g_q);
    float* p_xcat = symf(g_xcat);
    float* p_gates= symf(g_gates);
    float* p_H1   = symf(g_H1);

    const int M  = BB*SS;     // 2048

    // 1) embedding + reverse
    embed_rev_kernel<<<BB*SS, 128>>>(x, emb_src);

    // 2) layer-0 input GEMMs (M=2048, N=2048, K=512)
    {
        dim3 grid(M/128, (4*HH)/128);
        sgemm128<<<grid, 256>>>(p_embx, e0f_wih, e0f_b, p_xgF, M, 4*HH, EE, 0);
        sgemm128<<<grid, 256>>>(p_embx, e0b_wih, e0b_b, p_xgB, M, 4*HH, EE, 0);
    }

    // zero h (ping-pong) and c
    cudaMemsetAsync(p_hbuf, 0, sizeof(float)*2*2*2*BB*HH);
    cudaMemsetAsync(p_c,    0, sizeof(float)*2*2*BB*HH);

    // 3) layer-0 recurrence (both dirs per launch)
    {
        dim3 grid(HH/8, 2);
        for (int s = 0; s < SS; s++)
            enc_step<<<grid, 256>>>(e0f_whh, e0b_whh, 0, s);
    }

    // 4) layer-1 input GEMMs (K=1024)
    {
        dim3 grid(M/128, (4*HH)/128);
        sgemm128<<<grid, 256>>>(p_in1, e1f_wih, e1f_b, p_xgF, M, 4*HH, DDm, 0);
        sgemm128<<<grid, 256>>>(p_in1, e1b_wih, e1b_b, p_xgB, M, 4*HH, DDm, 0);
    }

    // 5) layer-1 recurrence
    {
        dim3 grid(HH/8, 2);
        for (int s = 0; s < SS; s++)
            enc_step<<<grid, 256>>>(e1f_whh, e1b_whh, 1, s);
    }

    // 6) Uenc = enc @ Ua^T + Ua_b   (M=2048, N=1024, K=1024)
    {
        dim3 grid(M/128, DDm/128);
        sgemm128<<<grid, 256>>>(p_enc, Ua_w, Ua_b, p_Uenc, M, DDm, DDm, 0);
    }

    // 7) decoder initial state
    dec_init<<<(BB*HH + 255)/256, 256>>>();

    // 8) decoder steps
    for (int t = 0; t < TT-1; t++) {
        // q = h1 @ Wa^T + Wa_b     (N=1024, K=1024)
        sgemm32<<<DDm/64, 256>>>(p_dh1, Wa_w, Wa_b, p_q, DDm, DDm, 0);
        // scores
        att_scores<<<BB*SS, 256>>>(va_w);
        // softmax + context + embedding
        softmax_ctx<<<BB, 256>>>(y, emb_tgt, t);
        // cell 0: gates = xcat@wih^T + b ; += h0@whh^T
        sgemm32<<<(4*DDm)/64, 256>>>(p_xcat, d0_wih, d0_b, p_gates, 4*DDm, EE+DDm, 0);
        sgemm32<<<(4*DDm)/64, 256>>>(p_dh0,  d0_whh, d0_b, p_gates, 4*DDm, DDm,    1);
        cell_update<<<(BB*DDm + 255)/256, 256>>>(p_dc0, p_dh0, nullptr, t);
        // cell 1: gates = h0@wih^T + b ; += h1@whh^T
        sgemm32<<<(4*DDm)/64, 256>>>(p_dh0, d1_wih, d1_b, p_gates, 4*DDm, DDm, 0);
        sgemm32<<<(4*DDm)/64, 256>>>(p_dh1, d1_whh, d1_b, p_gates, 4*DDm, DDm, 1);
        cell_update<<<(BB*DDm + 255)/256, 256>>>(p_dc1, p_dh1, p_H1, t);
    }

    // 9) deferred logits GEMM: out[b][t][:] = H1[t*32+b] @ fc_w^T + fc_b
    {
        int Mf = 63*BB;   // 2016
        dim3 grid((Mf + 127)/128, VV/128);
        sgemm128<<<grid, 256>>>(p_H1, fc_w, fc_b, out, Mf, VV, DDm, 1);
    }
}

// round 6
// speedup vs baseline: 1.7520x; 1.7520x over previous
#include <cuda_runtime.h>
#include <cuda_bf16.h>
#include <math.h>

// Problem constants
#define BB   32      // batch
#define SS   64      // src len
#define TT   64      // tgt len (63 decode steps)
#define EE   512     // embed dim
#define HH   512     // encoder hidden per dir
#define DDm  1024    // 2*H
#define VV   32000   // vocab

typedef unsigned long long ull;

// packed fp32x2 helpers (sm_103a FFMA2; numerically identical to scalar FMA)
__device__ __forceinline__ ull pk2(float x, float y) {
    ull r; asm("mov.b64 %0, {%1, %2};" : "=l"(r) : "f"(x), "f"(y)); return r;
}
__device__ __forceinline__ void fma2(ull& d, ull a, ull b) {
    asm("fma.rn.f32x2 %0, %1, %2, %0;" : "+l"(d) : "l"(a), "l"(b));
}
__device__ __forceinline__ float2 upk2(ull v) {
    float x, y; asm("mov.b64 {%0, %1}, %2;" : "=f"(x), "=f"(y) : "l"(v));
    return make_float2(x, y);
}

// ---------------------------------------------------------------------------
// Static device scratch (allocation-free rule)
// ---------------------------------------------------------------------------
__device__ __align__(16) float g_embx [BB*SS*EE];
__device__ __align__(16) float g_xgF  [BB*SS*4*HH];
__device__ __align__(16) float g_xgB  [BB*SS*4*HH];
__device__ __align__(16) float g_in1  [BB*SS*DDm];
__device__ __align__(16) float g_enc  [BB*SS*DDm];
__device__ __align__(16) float g_Uenc [BB*SS*DDm];
__device__ __align__(16) float g_hbuf [2*2*2*BB*HH];
__device__ __align__(16) float g_c    [2*2*BB*HH];
__device__ __align__(16) float g_dh0  [BB*DDm];
__device__ __align__(16) float g_dc0  [BB*DDm];
__device__ __align__(16) float g_dh1  [BB*DDm];
__device__ __align__(16) float g_dc1  [BB*DDm];
__device__ __align__(16) float g_q    [BB*DDm];
__device__ __align__(16) float g_sc   [BB*SS];
__device__ __align__(16) float g_xcat [BB*(EE+DDm)];
__device__ __align__(16) float g_gA   [BB*4*DDm];
__device__ __align__(16) float g_gB   [BB*4*DDm];
__device__ __align__(16) float g_H1   [63*BB*DDm];

__device__ __forceinline__ float sigf(float v) { return 1.0f/(1.0f + expf(-v)); }

// ---------------------------------------------------------------------------
// 1) embedding gather with source reversal
// ---------------------------------------------------------------------------
__global__ void embed_rev_kernel(const int* __restrict__ x,
                                 const float* __restrict__ emb_src) {
    int bs = blockIdx.x;
    int b = bs >> 6, s = bs & 63;
    int tok = x[b*SS + (SS-1 - s)];
    const float4* src = (const float4*)(emb_src + (size_t)tok*EE);
    float4* dst = (float4*)(g_embx + (size_t)bs*EE);
    for (int i = threadIdx.x; i < EE/4; i += blockDim.x) dst[i] = src[i];
}

// ---------------------------------------------------------------------------
// 2) SGEMM (TN) with packed f32x2 FMA: C[m][n] = A[m][:]*W[n][:] + bias[n]
//    BM=BN=128, BK=8, 256 threads, 8x8 per thread.
//    remap=1: output row r=(t*32+b) written to row (b*63+t)  (logits layout)
// ---------------------------------------------------------------------------
__global__ __launch_bounds__(256) void sgemm128(
    const float* __restrict__ A, const float* __restrict__ W,
    const float* __restrict__ bias, float* __restrict__ C,
    int M, int N, int K, int remap)
{
    __shared__ float As[8][132];
    __shared__ float Ws[8][132];
    int tid = threadIdx.x;
    int tx = tid & 15;          // N: 8 cols at n0 + tx*8
    int ty = tid >> 4;          // M: 8 rows at m0 + ty*8
    int m0 = blockIdx.x * 128;
    int n0 = blockIdx.y * 128;

    ull acc2[8][4];
    #pragma unroll
    for (int i = 0; i < 8; i++)
        #pragma unroll
        for (int j = 0; j < 4; j++) acc2[i][j] = 0ULL;

    int lr  = tid >> 1;
    int lk  = (tid & 1) * 4;

    for (int k0 = 0; k0 < K; k0 += 8) {
        float4 va;
        int gm = m0 + lr;
        if (gm < M) va = *(const float4*)(A + (size_t)gm*K + k0 + lk);
        else        va = make_float4(0.f,0.f,0.f,0.f);
        As[lk+0][lr]=va.x; As[lk+1][lr]=va.y; As[lk+2][lr]=va.z; As[lk+3][lr]=va.w;
        float4 vw = *(const float4*)(W + (size_t)(n0+lr)*K + k0 + lk);
        Ws[lk+0][lr]=vw.x; Ws[lk+1][lr]=vw.y; Ws[lk+2][lr]=vw.z; Ws[lk+3][lr]=vw.w;
        __syncthreads();

        #pragma unroll
        for (int kk = 0; kk < 8; kk++) {
            float4 a03 = *(const float4*)&As[kk][ty*8];
            float4 a47 = *(const float4*)&As[kk][ty*8+4];
            float4 w03 = *(const float4*)&Ws[kk][tx*8];
            float4 w47 = *(const float4*)&Ws[kk][tx*8+4];
            ull w01 = pk2(w03.x, w03.y);
            ull w23 = pk2(w03.z, w03.w);
            ull w45 = pk2(w47.x, w47.y);
            ull w67 = pk2(w47.z, w47.w);
            float av[8] = {a03.x,a03.y,a03.z,a03.w,a47.x,a47.y,a47.z,a47.w};
            #pragma unroll
            for (int i = 0; i < 8; i++) {
                ull aa = pk2(av[i], av[i]);
                fma2(acc2[i][0], aa, w01);
                fma2(acc2[i][1], aa, w23);
                fma2(acc2[i][2], aa, w45);
                fma2(acc2[i][3], aa, w67);
            }
        }
        __syncthreads();
    }

    #pragma unroll
    for (int i = 0; i < 8; i++) {
        int gm = m0 + ty*8 + i;
        if (gm >= M) continue;
        int orow = gm;
        if (remap) orow = (gm & 31)*63 + (gm >> 5);
        float* cr = C + (size_t)orow*N + n0 + tx*8;
        #pragma unroll
        for (int jp = 0; jp < 4; jp++) {
            float2 v = upk2(acc2[i][jp]);
            cr[2*jp+0] = v.x + bias[n0 + tx*8 + 2*jp+0];
            cr[2*jp+1] = v.y + bias[n0 + tx*8 + 2*jp+1];
        }
    }
}

// ---------------------------------------------------------------------------
// 3) Decoder GEMM, dual-matrix: blockIdx.y==0 computes C1 = A1@W1^T + bias,
//    blockIdx.y==1 computes C2 = A2@W2^T (no bias). BN=32, 256 threads,
//    4 outputs/thread (4 batch x 1 n), f32x2 FMA. grid.x = N/32.
//    K must be a multiple of 32.
// ---------------------------------------------------------------------------
__global__ __launch_bounds__(256) void dec_gemm(
    const float* __restrict__ A1, const float* __restrict__ W1,
    const float* __restrict__ bias, float* __restrict__ C1, int K1,
    const float* __restrict__ A2, const float* __restrict__ W2,
    float* __restrict__ C2, int K2, int N)
{
    const float* A; const float* W; const float* bs; float* C; int K;
    if (blockIdx.y == 0) { A = A1; W = W1; bs = bias;    C = C1; K = K1; }
    else                 { A = A2; W = W2; bs = nullptr; C = C2; K = K2; }

    __shared__ float As[32][34];   // [k][b], pad 34 keeps ull loads 8B-aligned
    __shared__ float Ws[32][33];   // [k][n]
    int tid = threadIdx.x;
    int tx = tid & 31;             // n within tile
    int ty = tid >> 5;             // b quad (0..7)
    int n0 = blockIdx.x * 32;

    ull acc01 = 0ULL, acc23 = 0ULL;

    int arow = tid >> 3;           // 0..31
    int ac4  = (tid & 7) * 4;      // 0..28

    for (int k0 = 0; k0 < K; k0 += 32) {
        float4 va = *(const float4*)(A + (size_t)arow*K + k0 + ac4);
        As[ac4+0][arow]=va.x; As[ac4+1][arow]=va.y;
        As[ac4+2][arow]=va.z; As[ac4+3][arow]=va.w;
        float4 vw = *(const float4*)(W + (size_t)(n0+arow)*K + k0 + ac4);
        Ws[ac4+0][arow]=vw.x; Ws[ac4+1][arow]=vw.y;
        Ws[ac4+2][arow]=vw.z; Ws[ac4+3][arow]=vw.w;
        __syncthreads();
        #pragma unroll
        for (int kk = 0; kk < 32; kk++) {
            float w = Ws[kk][tx];
            ull ww = pk2(w, w);
            ull a01 = *(const ull*)&As[kk][ty*4];
            ull a23 = *(const ull*)&As[kk][ty*4+2];
            fma2(acc01, a01, ww);
            fma2(acc23, a23, ww);
        }
        __syncthreads();
    }

    float bv = bs ? bs[n0 + tx] : 0.f;
    float2 v01 = upk2(acc01), v23 = upk2(acc23);
    int b = ty*4, n = n0 + tx;
    C[(size_t)(b+0)*N + n] = v01.x + bv;
    C[(size_t)(b+1)*N + n] = v01.y + bv;
    C[(size_t)(b+2)*N + n] = v23.x + bv;
    C[(size_t)(b+3)*N + n] = v23.y + bv;
}

// ---------------------------------------------------------------------------
// 4) Encoder recurrence step (unchanged from passing version)
// ---------------------------------------------------------------------------
__global__ __launch_bounds__(256) void enc_step(
    const float* __restrict__ whhF, const float* __restrict__ whhB,
    int layer, int step)
{
    __shared__ float sh[256*33];
    int tid = threadIdx.x;
    int dir = blockIdx.y;
    const float* whh = dir ? whhB : whhF;
    const float* xg  = dir ? g_xgB : g_xgF;
    int pp = step & 1;
    const float* hin  = g_hbuf + (size_t)(((layer*2+dir)*2) + pp)    * (BB*HH);
    float*       hout = g_hbuf + (size_t)(((layer*2+dir)*2) + (pp^1))* (BB*HH);
    float*       cb   = g_c    + (size_t)(layer*2+dir) * (BB*HH);
    float*       outb = layer ? g_enc : g_in1;
    int s = dir ? (63 - step) : step;

    int b = tid & 31;
    int j = blockIdx.x*8 + (tid >> 5);

    float a0=0.f, a1=0.f, a2=0.f, a3=0.f;
    for (int ch = 0; ch < 2; ch++) {
        for (int i = tid; i < 256*32; i += 256) {
            int bb = i >> 8, kk = i & 255;
            sh[kk*33 + bb] = hin[bb*HH + ch*256 + kk];
        }
        __syncthreads();
        const float4* w0 = (const float4*)(whh + (size_t)(0*HH + j)*HH + ch*256);
        const float4* w1 = (const float4*)(whh + (size_t)(1*HH + j)*HH + ch*256);
        const float4* w2 = (const float4*)(whh + (size_t)(2*HH + j)*HH + ch*256);
        const float4* w3 = (const float4*)(whh + (size_t)(3*HH + j)*HH + ch*256);
        #pragma unroll 4
        for (int k4 = 0; k4 < 64; k4++) {
            float4 v0 = w0[k4], v1 = w1[k4], v2 = w2[k4], v3 = w3[k4];
            float h0 = sh[(k4*4+0)*33 + b];
            float h1 = sh[(k4*4+1)*33 + b];
            float h2 = sh[(k4*4+2)*33 + b];
            float h3 = sh[(k4*4+3)*33 + b];
            a0 += v0.x*h0 + v0.y*h1 + v0.z*h2 + v0.w*h3;
            a1 += v1.x*h0 + v1.y*h1 + v1.z*h2 + v1.w*h3;
            a2 += v2.x*h0 + v2.y*h1 + v2.z*h2 + v2.w*h3;
            a3 += v3.x*h0 + v3.y*h1 + v3.z*h2 + v3.w*h3;
        }
        __syncthreads();
    }

    size_t row = (size_t)(b*SS + s) * (4*HH);
    float gi = xg[row + 0*HH + j] + a0;
    float gf = xg[row + 1*HH + j] + a1;
    float gg = xg[row + 2*HH + j] + a2;
    float go = xg[row + 3*HH + j] + a3;
    float cc = sigf(gf)*cb[b*HH + j] + sigf(gi)*tanhf(gg);
    float hh = sigf(go)*tanhf(cc);
    cb[b*HH + j] = cc;
    hout[b*HH + j] = hh;
    outb[(size_t)(b*SS + s)*DDm + dir*HH + j] = hh;
}

// ---------------------------------------------------------------------------
// 5) Decoder initial state
// ---------------------------------------------------------------------------
__global__ void dec_init() {
    int idx = blockIdx.x*256 + threadIdx.x;
    if (idx >= BB*HH) return;
    int b = idx >> 9, j = idx & 511;
    const int NP = BB*HH;
    float h0f = g_hbuf[(size_t)((0*2+0)*2+0)*NP + idx];
    float h0b = g_hbuf[(size_t)((0*2+1)*2+0)*NP + idx];
    float h1f = g_hbuf[(size_t)((1*2+0)*2+0)*NP + idx];
    float h1b = g_hbuf[(size_t)((1*2+1)*2+0)*NP + idx];
    float c0f = g_c[(size_t)(0*2+0)*NP + idx];
    float c0b = g_c[(size_t)(0*2+1)*NP + idx];
    float c1f = g_c[(size_t)(1*2+0)*NP + idx];
    float c1b = g_c[(size_t)(1*2+1)*NP + idx];
    g_dh0[b*DDm + j]       = h0f;  g_dh0[b*DDm + HH + j] = h0b;
    g_dc0[b*DDm + j]       = c0f;  g_dc0[b*DDm + HH + j] = c0b;
    g_dh1[b*DDm + j]       = h1f;  g_dh1[b*DDm + HH + j] = h1b;
    g_dc1[b*DDm + j]       = c1f;  g_dc1[b*DDm + HH + j] = c1b;
}

// ---------------------------------------------------------------------------
// 6) attention scores: sc[b][s] = sum_e va[e]*tanh(q[b][e] + Uenc[b][s][e])
// ---------------------------------------------------------------------------
__global__ __launch_bounds__(256) void att_scores(const float* __restrict__ va) {
    __shared__ float red[256];
    int bs = blockIdx.x;
    int b = bs >> 6;
    const float* u  = g_Uenc + (size_t)bs*DDm;
    const float* qq = g_q + (size_t)b*DDm;
    int tid = threadIdx.x;
    float p = 0.f;
    for (int e = tid; e < DDm; e += 256)
        p += va[e]*tanhf(qq[e] + u[e]);
    red[tid] = p; __syncthreads();
    for (int off = 128; off > 0; off >>= 1) {
        if (tid < off) red[tid] += red[tid+off];
        __syncthreads();
    }
    if (tid == 0) g_sc[bs] = red[0];
}

// ---------------------------------------------------------------------------
// 7) softmax + context + target-embedding gather -> g_xcat[32][1536]
// ---------------------------------------------------------------------------
__global__ __launch_bounds__(256) void softmax_ctx(
    const int* __restrict__ y, const float* __restrict__ emb_tgt, int t)
{
    __shared__ float w[SS];
    int b = blockIdx.x;
    int tid = threadIdx.x;
    if (tid < SS) w[tid] = g_sc[b*SS + tid];
    __syncthreads();
    if (tid == 0) {
        float mx = w[0];
        for (int s = 1; s < SS; s++) mx = fmaxf(mx, w[s]);
        float sm = 0.f;
        for (int s = 0; s < SS; s++) { w[s] = expf(w[s]-mx); sm += w[s]; }
        float inv = 1.0f/sm;
        for (int s = 0; s < SS; s++) w[s] *= inv;
    }
    __syncthreads();
    for (int d = tid; d < DDm; d += 256) {
        float acc = 0.f;
        const float* e = g_enc + (size_t)(b*SS)*DDm + d;
        #pragma unroll 4
        for (int s = 0; s < SS; s++) acc += w[s]*e[(size_t)s*DDm];
        g_xcat[(size_t)b*(EE+DDm) + EE + d] = acc;
    }
    int tok = y[b*TT + t];
    const float* es = emb_tgt + (size_t)tok*EE;
    for (int e = tid; e < EE; e += 256)
        g_xcat[(size_t)b*(EE+DDm) + e] = es[e];
}

// ---------------------------------------------------------------------------
// 8) LSTM cell pointwise: gates = gA + gB (bias already in gA)
// ---------------------------------------------------------------------------
__global__ void cell_update2(float* __restrict__ cbuf, float* __restrict__ hbuf,
                             float* __restrict__ H1, int t)
{
    int idx = blockIdx.x*256 + threadIdx.x;
    if (idx >= BB*DDm) return;
    int b = idx >> 10, j = idx & 1023;
    const float* ga = g_gA + (size_t)b*4*DDm;
    const float* gb = g_gB + (size_t)b*4*DDm;
    float gi = ga[j]         + gb[j];
    float gf = ga[DDm + j]   + gb[DDm + j];
    float gg = ga[2*DDm + j] + gb[2*DDm + j];
    float go = ga[3*DDm + j] + gb[3*DDm + j];
    float cc = sigf(gf)*cbuf[idx] + sigf(gi)*tanhf(gg);
    float hh = sigf(go)*tanhf(cc);
    cbuf[idx] = cc;
    hbuf[idx] = hh;
    if (H1) H1[((size_t)t*BB + b)*DDm + j] = hh;
}

// ---------------------------------------------------------------------------
// host driver
// ---------------------------------------------------------------------------
static float* symf(const void* s) {
    void* p = nullptr;
    cudaGetSymbolAddress(&p, s);
    return (float*)p;
}

extern "C" void kernel_launch(void* const* d_in, const int* in_sizes, int n_in,
                              void* d_out, int out_size) {
    const int*   x        = (const int*)  d_in[0];
    const int*   y        = (const int*)  d_in[1];
    const float* emb_src  = (const float*)d_in[2];
    const float* emb_tgt  = (const float*)d_in[3];
    const float* e0f_wih  = (const float*)d_in[4];
    const float* e0f_whh  = (const float*)d_in[5];
    const float* e0f_b    = (const float*)d_in[6];
    const float* e0b_wih  = (const float*)d_in[7];
    const float* e0b_whh  = (const float*)d_in[8];
    const float* e0b_b    = (const float*)d_in[9];
    const float* e1f_wih  = (const float*)d_in[10];
    const float* e1f_whh  = (const float*)d_in[11];
    const float* e1f_b    = (const float*)d_in[12];
    const float* e1b_wih  = (const float*)d_in[13];
    const float* e1b_whh  = (const float*)d_in[14];
    const float* e1b_b    = (const float*)d_in[15];
    const float* Wa_w     = (const float*)d_in[16];
    const float* Wa_b     = (const float*)d_in[17];
    const float* Ua_w     = (const float*)d_in[18];
    const float* Ua_b     = (const float*)d_in[19];
    const float* va_w     = (const float*)d_in[20];
    const float* d0_wih   = (const float*)d_in[21];
    const float* d0_whh   = (const float*)d_in[22];
    const float* d0_b     = (const float*)d_in[23];
    const float* d1_wih   = (const float*)d_in[24];
    const float* d1_whh   = (const float*)d_in[25];
    const float* d1_b     = (const float*)d_in[26];
    const float* fc_w     = (const float*)d_in[27];
    const float* fc_b     = (const float*)d_in[28];
    float* out = (float*)d_out;

    float* p_embx = symf(g_embx);
    float* p_xgF  = symf(g_xgF);
    float* p_xgB  = symf(g_xgB);
    float* p_in1  = symf(g_in1);
    float* p_enc  = symf(g_enc);
    float* p_Uenc = symf(g_Uenc);
    float* p_hbuf = symf(g_hbuf);
    float* p_c    = symf(g_c);
    float* p_dh0  = symf(g_dh0);
    float* p_dc0  = symf(g_dc0);
    float* p_dh1  = symf(g_dh1);
    float* p_dc1  = symf(g_dc1);
    float* p_q    = symf(g_q);
    float* p_xcat = symf(g_xcat);
    float* p_gA   = symf(g_gA);
    float* p_gB   = symf(g_gB);
    float* p_H1   = symf(g_H1);

    const int M  = BB*SS;     // 2048

    // 1) embedding + reverse
    embed_rev_kernel<<<BB*SS, 128>>>(x, emb_src);

    // 2) layer-0 input GEMMs
    {
        dim3 grid(M/128, (4*HH)/128);
        sgemm128<<<grid, 256>>>(p_embx, e0f_wih, e0f_b, p_xgF, M, 4*HH, EE, 0);
        sgemm128<<<grid, 256>>>(p_embx, e0b_wih, e0b_b, p_xgB, M, 4*HH, EE, 0);
    }

    cudaMemsetAsync(p_hbuf, 0, sizeof(float)*2*2*2*BB*HH);
    cudaMemsetAsync(p_c,    0, sizeof(float)*2*2*BB*HH);

    // 3) layer-0 recurrence
    {
        dim3 grid(HH/8, 2);
        for (int s = 0; s < SS; s++)
            enc_step<<<grid, 256>>>(e0f_whh, e0b_whh, 0, s);
    }

    // 4) layer-1 input GEMMs
    {
        dim3 grid(M/128, (4*HH)/128);
        sgemm128<<<grid, 256>>>(p_in1, e1f_wih, e1f_b, p_xgF, M, 4*HH, DDm, 0);
        sgemm128<<<grid, 256>>>(p_in1, e1b_wih, e1b_b, p_xgB, M, 4*HH, DDm, 0);
    }

    // 5) layer-1 recurrence
    {
        dim3 grid(HH/8, 2);
        for (int s = 0; s < SS; s++)
            enc_step<<<grid, 256>>>(e1f_whh, e1b_whh, 1, s);
    }

    // 6) Uenc = enc @ Ua^T + Ua_b
    {
        dim3 grid(M/128, DDm/128);
        sgemm128<<<grid, 256>>>(p_enc, Ua_w, Ua_b, p_Uenc, M, DDm, DDm, 0);
    }

    // 7) decoder initial state
    dec_init<<<(BB*HH + 255)/256, 256>>>();

    // 8) decoder steps (7 launches per step)
    for (int t = 0; t < TT-1; t++) {
        // q = h1 @ Wa^T + Wa_b
        dec_gemm<<<dim3(DDm/32, 1), 256>>>(p_dh1, Wa_w, Wa_b, p_q, DDm,
                                           nullptr, nullptr, nullptr, 32, DDm);
        att_scores<<<BB*SS, 256>>>(va_w);
        softmax_ctx<<<BB, 256>>>(y, emb_tgt, t);
        // cell 0 gates: gA = xcat@d0_wih^T + b ; gB = h0@d0_whh^T
        dec_gemm<<<dim3((4*DDm)/32, 2), 256>>>(p_xcat, d0_wih, d0_b, p_gA, EE+DDm,
                                               p_dh0, d0_whh, p_gB, DDm, 4*DDm);
        cell_update2<<<(BB*DDm + 255)/256, 256>>>(p_dc0, p_dh0, nullptr, t);
        // cell 1 gates: gA = h0@d1_wih^T + b ; gB = h1@d1_whh^T
        dec_gemm<<<dim3((4*DDm)/32, 2), 256>>>(p_dh0, d1_wih, d1_b, p_gA, DDm,
                                               p_dh1, d1_whh, p_gB, DDm, 4*DDm);
        cell_update2<<<(BB*DDm + 255)/256, 256>>>(p_dc1, p_dh1, p_H1, t);
    }

    // 9) deferred logits GEMM
    {
        int Mf = 63*BB;   // 2016
        dim3 grid((Mf + 127)/128, VV/128);
        sgemm128<<<grid, 256>>>(p_H1, fc_w, fc_b, out, Mf, VV, DDm, 1);
    }
}